// round 1
// baseline (speedup 1.0000x reference)
#include <cuda_runtime.h>
#include <math.h>

// Problem shape (fixed by the dataset)
constexpr int Bn = 16;     // batch
constexpr int Tn = 512;    // time
constexpr int Hn = 512;    // hidden (K)
constexpr int Vn = 4096;   // vocab (N)
constexpr int Ln = 64;     // max label len
constexpr int Jn = 66;     // gathered emissions per (b,t): blank + 64 labels (padded to 66)
constexpr int Smax = 2 * Ln + 1;  // 129 extended states
constexpr float NEGF = -1e30f;

// Scratch (static __device__ allocation — allowed; no cudaMalloc)
__device__ float g_logits[(size_t)Bn * Tn * Vn];  // 128 MiB
__device__ float g_emit[(size_t)Bn * Tn * Jn];    // gathered log-probs (logit - lse)

// ---------------------------------------------------------------------------
// Kernel 1: SGEMM  logits[M=B*T, N=V] = hs[M,K] @ W[K,N] + bias[N]
// Classic 128x128x16 register-tiled, double-buffered smem, 256 threads,
// 8x8 micro-tile per thread.
// ---------------------------------------------------------------------------
constexpr int BM = 128, BN = 128, BK = 16;

__global__ __launch_bounds__(256) void gemm_kernel(const float* __restrict__ A,
                                                   const float* __restrict__ Wm,
                                                   const float* __restrict__ bias) {
    __shared__ __align__(16) float As[2][BK][BM];
    __shared__ __align__(16) float Bs[2][BK][BN];

    const int tid = threadIdx.x;
    const int bm = blockIdx.y * BM;
    const int bn = blockIdx.x * BN;

    const int aRow = tid >> 2;          // 0..63
    const int aCol = (tid & 3) << 2;    // 0,4,8,12
    const int bRow = tid >> 5;          // 0..7
    const int bCol = (tid & 31) << 2;   // 0..124
    const int tx = tid & 15;
    const int ty = tid >> 4;

    // Prologue: fill buffer 0
    {
#pragma unroll
        for (int r = 0; r < 2; r++) {
            float4 v = *(const float4*)(A + (size_t)(bm + aRow + 64 * r) * Hn + aCol);
            As[0][aCol + 0][aRow + 64 * r] = v.x;
            As[0][aCol + 1][aRow + 64 * r] = v.y;
            As[0][aCol + 2][aRow + 64 * r] = v.z;
            As[0][aCol + 3][aRow + 64 * r] = v.w;
        }
#pragma unroll
        for (int r = 0; r < 2; r++) {
            float4 v = *(const float4*)(Wm + (size_t)(bRow + 8 * r) * Vn + bn + bCol);
            *(float4*)&Bs[0][bRow + 8 * r][bCol] = v;
        }
    }
    __syncthreads();

    float acc[8][8];
#pragma unroll
    for (int i = 0; i < 8; i++)
#pragma unroll
        for (int j = 0; j < 8; j++) acc[i][j] = 0.f;

    const int NK = Hn / BK;  // 32
    float4 sA[2], sB[2];

    for (int kk = 0; kk < NK; kk++) {
        const int cur = kk & 1;
        if (kk + 1 < NK) {
            const int k0 = (kk + 1) * BK;
#pragma unroll
            for (int r = 0; r < 2; r++)
                sA[r] = *(const float4*)(A + (size_t)(bm + aRow + 64 * r) * Hn + k0 + aCol);
#pragma unroll
            for (int r = 0; r < 2; r++)
                sB[r] = *(const float4*)(Wm + (size_t)(k0 + bRow + 8 * r) * Vn + bn + bCol);
        }
#pragma unroll
        for (int k = 0; k < BK; k++) {
            float ra[8], rb[8];
            *(float4*)&ra[0] = *(const float4*)&As[cur][k][ty * 8];
            *(float4*)&ra[4] = *(const float4*)&As[cur][k][ty * 8 + 4];
            *(float4*)&rb[0] = *(const float4*)&Bs[cur][k][tx * 8];
            *(float4*)&rb[4] = *(const float4*)&Bs[cur][k][tx * 8 + 4];
#pragma unroll
            for (int i = 0; i < 8; i++)
#pragma unroll
                for (int j = 0; j < 8; j++)
                    acc[i][j] = fmaf(ra[i], rb[j], acc[i][j]);
        }
        if (kk + 1 < NK) {
            const int nxt = cur ^ 1;
#pragma unroll
            for (int r = 0; r < 2; r++) {
                As[nxt][aCol + 0][aRow + 64 * r] = sA[r].x;
                As[nxt][aCol + 1][aRow + 64 * r] = sA[r].y;
                As[nxt][aCol + 2][aRow + 64 * r] = sA[r].z;
                As[nxt][aCol + 3][aRow + 64 * r] = sA[r].w;
            }
#pragma unroll
            for (int r = 0; r < 2; r++)
                *(float4*)&Bs[nxt][bRow + 8 * r][bCol] = sB[r];
        }
        __syncthreads();
    }

    // Epilogue: += bias, write scratch
    float bv[8];
    *(float4*)&bv[0] = *(const float4*)(bias + bn + tx * 8);
    *(float4*)&bv[4] = *(const float4*)(bias + bn + tx * 8 + 4);
#pragma unroll
    for (int i = 0; i < 8; i++) {
        float* cp = g_logits + (size_t)(bm + ty * 8 + i) * Vn + bn + tx * 8;
        float4 o0, o1;
        o0.x = acc[i][0] + bv[0]; o0.y = acc[i][1] + bv[1];
        o0.z = acc[i][2] + bv[2]; o0.w = acc[i][3] + bv[3];
        o1.x = acc[i][4] + bv[4]; o1.y = acc[i][5] + bv[5];
        o1.z = acc[i][6] + bv[6]; o1.w = acc[i][7] + bv[7];
        *(float4*)cp = o0;
        *(float4*)(cp + 4) = o1;
    }
}

// ---------------------------------------------------------------------------
// Kernel 2: per-row logsumexp over V + gather emissions at the 65 needed ids.
// One block (256 thr) per (b,t) row. Row kept in registers (16 elems/thread).
// ---------------------------------------------------------------------------
__global__ __launch_bounds__(256) void lse_gather_kernel(const int* __restrict__ ys) {
    const int row = blockIdx.x;   // b*Tn + t
    const int tid = threadIdx.x;
    const float* rp = g_logits + (size_t)row * Vn;

    float v[16];
    float mx = -3.4e38f;
#pragma unroll
    for (int i = 0; i < 16; i++) {
        v[i] = rp[tid + 256 * i];
        mx = fmaxf(mx, v[i]);
    }
    __shared__ float smax[8];
    __shared__ float ssum[8];
    __shared__ float slse;
#pragma unroll
    for (int o = 16; o > 0; o >>= 1) mx = fmaxf(mx, __shfl_xor_sync(0xffffffffu, mx, o));
    if ((tid & 31) == 0) smax[tid >> 5] = mx;
    __syncthreads();
    float m = smax[0];
#pragma unroll
    for (int i = 1; i < 8; i++) m = fmaxf(m, smax[i]);

    float s = 0.f;
#pragma unroll
    for (int i = 0; i < 16; i++) s += expf(v[i] - m);
#pragma unroll
    for (int o = 16; o > 0; o >>= 1) s += __shfl_xor_sync(0xffffffffu, s, o);
    if ((tid & 31) == 0) ssum[tid >> 5] = s;
    __syncthreads();
    if (tid == 0) {
        float tot = 0.f;
#pragma unroll
        for (int i = 0; i < 8; i++) tot += ssum[i];
        slse = m + logf(tot);
    }
    __syncthreads();

    if (tid < 65) {
        const int b = row >> 9;  // / Tn
        const int vid = (tid == 0) ? 0 : ys[b * Ln + tid - 1];
        g_emit[(size_t)row * Jn + tid] = rp[vid] - slse;
    }
}

// ---------------------------------------------------------------------------
// Kernel 3: CTC forward DP. One warp per batch element, 5 states per lane
// (s = slot*32 + lane), neighbor access via warp shuffles. Single block.
// ---------------------------------------------------------------------------
__device__ __forceinline__ float lae(float x, float y) {
    float m = fmaxf(x, y);
    float d = fabsf(x - y);
    return m + log1pf(expf(-d));
}

__global__ __launch_bounds__(512) void ctc_dp_kernel(const int* __restrict__ ys,
                                                     const int* __restrict__ hlen,
                                                     const int* __restrict__ ylen,
                                                     float* __restrict__ out) {
    const int w = threadIdx.x >> 5;   // batch
    const int lane = threadIdx.x & 31;

    float a[5];
    int jj[5];
    bool skipf[5];
#pragma unroll
    for (int sl = 0; sl < 5; sl++) {
        const int s = sl * 32 + lane;
        const bool valid = (s < Smax);
        int j = 0;
        bool sk = false;
        if ((s & 1) == 1 && valid) {
            const int li = (s - 1) >> 1;
            j = li + 1;
            const int lab = ys[w * Ln + li];
            if (s >= 3) {
                const int labp = ys[w * Ln + li - 1];
                sk = (lab != 0) && (lab != labp);
            }
        }
        jj[sl] = j;
        skipf[sl] = sk;
        const float* e0 = g_emit + (size_t)(w * Tn) * Jn;
        if (s == 0)      a[sl] = e0[0];
        else if (s == 1) a[sl] = e0[1];
        else             a[sl] = NEGF;
    }

    const int inlen = hlen[w];
    for (int t = 1; t < Tn; t++) {
        if (t >= inlen) break;  // uniform per warp
        const float* et = g_emit + (size_t)(w * Tn + t) * Jn;
        float e[5];
#pragma unroll
        for (int sl = 0; sl < 5; sl++) e[sl] = et[jj[sl]];

        float an[5];
#pragma unroll
        for (int sl = 0; sl < 5; sl++) {
            float up1 = __shfl_up_sync(0xffffffffu, a[sl], 1);
            float up2 = __shfl_up_sync(0xffffffffu, a[sl], 2);
            float pm1 = NEGF, pm2 = NEGF;
            if (sl > 0) {
                pm1 = __shfl_sync(0xffffffffu, a[sl - 1], 31);
                pm2 = __shfl_sync(0xffffffffu, a[sl - 1], 30);
            }
            float am1 = (lane == 0) ? pm1 : up1;
            float am2 = (lane == 0) ? pm2 : ((lane == 1) ? pm1 : up2);
            float comb = lae(a[sl], am1);
            if (skipf[sl]) comb = lae(comb, am2);
            an[sl] = comb + e[sl];
        }
#pragma unroll
        for (int sl = 0; sl < 5; sl++) a[sl] = an[sl];
    }

    __shared__ float sal[Bn][Smax + 3];
    __shared__ float wll[Bn];
#pragma unroll
    for (int sl = 0; sl < 5; sl++) {
        const int s = sl * 32 + lane;
        if (s < Smax) sal[w][s] = a[sl];
    }
    __syncthreads();
    if (lane == 0) {
        const int s2 = 2 * ylen[w];
        wll[w] = lae(sal[w][s2], sal[w][s2 - 1]);
    }
    __syncthreads();
    if (threadIdx.x == 0) {
        float acc = 0.f;
#pragma unroll
        for (int i = 0; i < Bn; i++) acc += -wll[i];
        out[0] = acc / (float)Bn;
    }
}

// ---------------------------------------------------------------------------
extern "C" void kernel_launch(void* const* d_in, const int* in_sizes, int n_in,
                              void* d_out, int out_size) {
    const float* hs   = (const float*)d_in[0];  // [B,T,H]
    const int*   hlen = (const int*)d_in[1];    // [B]
    const int*   ys   = (const int*)d_in[2];    // [B,L]
    const int*   ylen = (const int*)d_in[3];    // [B]
    const float* Wm   = (const float*)d_in[4];  // [H,V]
    const float* bias = (const float*)d_in[5];  // [V]
    float* out = (float*)d_out;

    dim3 grid(Vn / BN, (Bn * Tn) / BM);  // (32, 64)
    gemm_kernel<<<grid, 256>>>(hs, Wm, bias);
    lse_gather_kernel<<<Bn * Tn, 256>>>(ys);
    ctc_dp_kernel<<<1, 512>>>(ys, hlen, ylen, out);
}

// round 3
// speedup vs baseline: 2.7814x; 2.7814x over previous
#include <cuda_runtime.h>
#include <cuda_bf16.h>
#include <math.h>
#include <stdint.h>

// ---------------------------------------------------------------- shapes
constexpr int Bn = 16, Tn = 512, Hn = 512, Vn = 4096, Ln = 64, Jn = 66;
constexpr int Mn = Bn * Tn;            // 8192 GEMM rows
constexpr int Smax = 2 * Ln + 1;       // 129 CTC states
constexpr float NEGF = -1e30f;

// ---------------------------------------------------------------- scratch
__device__ __nv_bfloat16 g_Abf[(size_t)Mn * Hn];    // 8 MB
__device__ __nv_bfloat16 g_Bbf[(size_t)Vn * Hn];    // 4 MB  W^T [V,K] K-major
__device__ float2        g_part[(size_t)Mn * 128];  // per-row (max,sumexp) partials
__device__ float         g_gath[(size_t)Mn * Jn];   // gathered logits at label ids
__device__ float         g_emit[(size_t)Mn * Jn];   // log-probs at label ids
__device__ int           g_rep[Bn * Jn];            // duplicate-label representative
__device__ float         g_ll[Bn];

// ---------------------------------------------------------------- helpers
__device__ __forceinline__ uint32_t smem_u32(const void* p) {
    uint32_t a;
    asm("{ .reg .u64 t; cvta.to.shared.u64 t, %1; cvt.u32.u64 %0, t; }" : "=r"(a) : "l"(p));
    return a;
}
__device__ __forceinline__ void ldm_x4(uint32_t* r, uint32_t addr) {
    asm volatile("ldmatrix.sync.aligned.m8n8.x4.shared.b16 {%0,%1,%2,%3}, [%4];"
                 : "=r"(r[0]), "=r"(r[1]), "=r"(r[2]), "=r"(r[3]) : "r"(addr));
}
__device__ __forceinline__ void ldm_x2(uint32_t* r, uint32_t addr) {
    asm volatile("ldmatrix.sync.aligned.m8n8.x2.shared.b16 {%0,%1}, [%2];"
                 : "=r"(r[0]), "=r"(r[1]) : "r"(addr));
}
__device__ __forceinline__ void mma_bf16(float* d, const uint32_t* a, const uint32_t* b) {
    asm volatile("mma.sync.aligned.m16n8k16.row.col.f32.bf16.bf16.f32 "
                 "{%0,%1,%2,%3}, {%4,%5,%6,%7}, {%8,%9}, {%0,%1,%2,%3};"
                 : "+f"(d[0]), "+f"(d[1]), "+f"(d[2]), "+f"(d[3])
                 : "r"(a[0]), "r"(a[1]), "r"(a[2]), "r"(a[3]), "r"(b[0]), "r"(b[1]));
}

// ---------------------------------------------------------------- convert A (fp32 -> bf16)
__global__ __launch_bounds__(256) void convA_kernel(const float* __restrict__ hs) {
    size_t i = (size_t)blockIdx.x * 256 + threadIdx.x;
    float4 v = ((const float4*)hs)[i];
    __nv_bfloat162 lo = __floats2bfloat162_rn(v.x, v.y);
    __nv_bfloat162 hi = __floats2bfloat162_rn(v.z, v.w);
    uint2 u;
    u.x = *(uint32_t*)&lo;
    u.y = *(uint32_t*)&hi;
    ((uint2*)g_Abf)[i] = u;
}

// ---------------------------------------------------------------- convert+transpose W: [K,V] -> [V,K] bf16
__global__ __launch_bounds__(256) void convB_kernel(const float* __restrict__ W) {
    __shared__ float tile[32][33];
    const int v0 = blockIdx.x * 32, k0 = blockIdx.y * 32;
    const int tx = threadIdx.x, ty = threadIdx.y;
#pragma unroll
    for (int j = 0; j < 4; j++)
        tile[ty + 8 * j][tx] = W[(size_t)(k0 + ty + 8 * j) * Vn + v0 + tx];
    __syncthreads();
#pragma unroll
    for (int j = 0; j < 4; j++) {
        int vl = ty + 8 * j;
        g_Bbf[(size_t)(v0 + vl) * Hn + k0 + tx] = __float2bfloat16(tile[tx][vl]);
    }
}

// ---------------------------------------------------------------- duplicate-label representative table
__global__ void rep_kernel(const int* __restrict__ ys) {
    const int b = blockIdx.x, j = threadIdx.x;
    if (j >= 65) return;
    const int vid = (j == 0) ? 0 : ys[b * Ln + j - 1];
    int r = j;
    for (int q = 0; q < j; q++) {
        const int vq = (q == 0) ? 0 : ys[b * Ln + q - 1];
        if (vq == vid) { r = q; break; }
    }
    g_rep[b * Jn + j] = r;
}

// ---------------------------------------------------------------- HMMA GEMM + fused LSE partials + label gather
// CTA tile 128x128, BK=32, 8 warps (warp tile 64x32), double-buffered smem.
// Smem layout per operand tile: chunk-major [4 chunks of 16B][128 rows] ->
// every ldmatrix 8x8 fragment is 128B contiguous (conflict-free).
__global__ __launch_bounds__(256, 2) void gemm_mma_kernel(const int* __restrict__ ys,
                                                          const float* __restrict__ bias) {
    __shared__ __align__(1024) char sm[2][16384];  // [buf][A(8K) | B(8K)]
    __shared__ float sbias[128];
    __shared__ int stable[128];

    const int tid = threadIdx.x, w = tid >> 5, lane = tid & 31;
    const int bn = blockIdx.x * 128, bm = blockIdx.y * 128;
    const int b = blockIdx.y >> 2;  // batch of this 128-row block (512/128=4)

    if (tid < 128) { sbias[tid] = bias[bn + tid]; stable[tid] = -1; }
    __syncthreads();
    if (tid == 0) {
        for (int j = 0; j < 65; j++) {
            const int vid = (j == 0) ? 0 : ys[b * Ln + j - 1];
            const int idx = vid - bn;
            if (idx >= 0 && idx < 128 && stable[idx] < 0) stable[idx] = j;
        }
    }

    // global load mapping: 2 threads per row, each owns 2 x 16B chunks
    const int row = tid >> 1, kp = tid & 1;
    const __nv_bfloat16* gA = g_Abf + (size_t)(bm + row) * Hn + kp * 16;
    const __nv_bfloat16* gB = g_Bbf + (size_t)(bn + row) * Hn + kp * 16;
    const uint32_t smb = smem_u32(sm);
    const uint32_t stsOff = (uint32_t)(kp * 2) * 2048 + (uint32_t)row * 16;

    // ldmatrix per-lane base addresses
    const int wm = w >> 2, wn = w & 3;
    const uint32_t aBase = smb + (uint32_t)(wm * 64 + (lane & 15)) * 16 + (uint32_t)(lane >> 4) * 2048;
    const uint32_t bBase = smb + 8192 + (uint32_t)(wn * 32 + (lane & 7)) * 16 + (uint32_t)((lane >> 3) & 1) * 2048;

    float acc[4][4][4];
#pragma unroll
    for (int mi = 0; mi < 4; mi++)
#pragma unroll
        for (int ni = 0; ni < 4; ni++)
#pragma unroll
            for (int e = 0; e < 4; e++) acc[mi][ni][e] = 0.f;

    uint4 va0, va1, vb0, vb1;
    // prologue: load chunk 0, store to buf 0
    va0 = *(const uint4*)(gA);     va1 = *(const uint4*)(gA + 8);
    vb0 = *(const uint4*)(gB);     vb1 = *(const uint4*)(gB + 8);
    {
        char* base = sm[0];
        *(uint4*)(base + stsOff) = va0;
        *(uint4*)(base + stsOff + 2048) = va1;
        *(uint4*)(base + 8192 + stsOff) = vb0;
        *(uint4*)(base + 8192 + stsOff + 2048) = vb1;
    }
    __syncthreads();

    const int NC = Hn / 32;  // 16
    for (int c = 0; c < NC; c++) {
        const int cur = c & 1;
        if (c + 1 < NC) {
            va0 = *(const uint4*)(gA + (c + 1) * 32);
            va1 = *(const uint4*)(gA + (c + 1) * 32 + 8);
            vb0 = *(const uint4*)(gB + (c + 1) * 32);
            vb1 = *(const uint4*)(gB + (c + 1) * 32 + 8);
        }
        const uint32_t bufOff = (uint32_t)cur * 16384;
#pragma unroll
        for (int kk = 0; kk < 2; kk++) {
            uint32_t aF[4][4], bF[4][2];
#pragma unroll
            for (int mi = 0; mi < 4; mi++)
                ldm_x4(aF[mi], aBase + bufOff + kk * 4096 + mi * 256);
#pragma unroll
            for (int ni = 0; ni < 4; ni++)
                ldm_x2(bF[ni], bBase + bufOff + kk * 4096 + ni * 128);
#pragma unroll
            for (int mi = 0; mi < 4; mi++)
#pragma unroll
                for (int ni = 0; ni < 4; ni++)
                    mma_bf16(acc[mi][ni], aF[mi], bF[ni]);
        }
        if (c + 1 < NC) {
            char* base = sm[(c + 1) & 1];
            *(uint4*)(base + stsOff) = va0;
            *(uint4*)(base + stsOff + 2048) = va1;
            *(uint4*)(base + 8192 + stsOff) = vb0;
            *(uint4*)(base + 8192 + stsOff + 2048) = vb1;
        }
        __syncthreads();
    }

    // ---- fused epilogue: bias, row (max,sumexp) partials, label gather
    const int tq = lane >> 2, lq = lane & 3;
#pragma unroll
    for (int mi = 0; mi < 4; mi++) {
#pragma unroll
        for (int h = 0; h < 2; h++) {
            const int rloc = wm * 64 + mi * 16 + h * 8 + tq;
            const size_t grow = (size_t)(bm + rloc);
            float v[8];
            float mx = -3.4e38f;
#pragma unroll
            for (int ni = 0; ni < 4; ni++)
#pragma unroll
                for (int e = 0; e < 2; e++) {
                    float f = acc[mi][ni][h * 2 + e] + sbias[wn * 32 + ni * 8 + lq * 2 + e];
                    v[ni * 2 + e] = f;
                    mx = fmaxf(mx, f);
                }
            float sum = 0.f;
#pragma unroll
            for (int i = 0; i < 8; i++) sum += __expf(v[i] - mx);
            // reduce across the 4 lanes sharing this row (lq = 0..3)
#pragma unroll
            for (int o = 1; o <= 2; o <<= 1) {
                float mo = __shfl_xor_sync(0xffffffffu, mx, o);
                float so = __shfl_xor_sync(0xffffffffu, sum, o);
                float m2 = fmaxf(mx, mo);
                sum = sum * __expf(mx - m2) + so * __expf(mo - m2);
                mx = m2;
            }
            if (lq == 0)
                g_part[grow * 128 + blockIdx.x * 4 + wn] = make_float2(mx, sum);
            // gather label logits
#pragma unroll
            for (int ni = 0; ni < 4; ni++)
#pragma unroll
                for (int e = 0; e < 2; e++) {
                    const int cidx = wn * 32 + ni * 8 + lq * 2 + e;
                    const int slot = stable[cidx];
                    if (slot >= 0) g_gath[grow * Jn + slot] = v[ni * 2 + e];
                }
        }
    }
}

// ---------------------------------------------------------------- LSE reduce (128 partials/row) + emit
__global__ __launch_bounds__(256) void lse_emit_kernel() {
    const int warp = threadIdx.x >> 5, lane = threadIdx.x & 31;
    const size_t row = (size_t)blockIdx.x * 8 + warp;
    const int b = (int)(row >> 9);
    float2 p[4];
#pragma unroll
    for (int i = 0; i < 4; i++) p[i] = g_part[row * 128 + lane + 32 * i];
    float m = fmaxf(fmaxf(p[0].x, p[1].x), fmaxf(p[2].x, p[3].x));
#pragma unroll
    for (int o = 16; o > 0; o >>= 1) m = fmaxf(m, __shfl_xor_sync(0xffffffffu, m, o));
    float s = 0.f;
#pragma unroll
    for (int i = 0; i < 4; i++) s += p[i].y * __expf(p[i].x - m);
#pragma unroll
    for (int o = 16; o > 0; o >>= 1) s += __shfl_xor_sync(0xffffffffu, s, o);
    const float lse = m + __logf(s);
#pragma unroll
    for (int j = lane; j < 65; j += 32)
        g_emit[row * Jn + j] = g_gath[row * Jn + g_rep[b * Jn + j]] - lse;
}

// ---------------------------------------------------------------- CTC forward DP: one SM per batch
__device__ __forceinline__ float lae(float x, float y) {
    float mx = fmaxf(x, y);
    float d = fminf(x, y) - mx;
    return mx + __logf(1.f + __expf(d));
}

__global__ __launch_bounds__(32) void ctc_dp_kernel(const int* __restrict__ ys,
                                                    const int* __restrict__ hlen,
                                                    const int* __restrict__ ylen) {
    const int b = blockIdx.x, lane = threadIdx.x;

    float a[5];
    int jj[5];
    bool skipf[5];
    const float* eb = g_emit + (size_t)b * Tn * Jn;
#pragma unroll
    for (int sl = 0; sl < 5; sl++) {
        const int s = sl * 32 + lane;
        int j = 0;
        bool sk = false;
        if ((s & 1) == 1 && s < Smax) {
            const int li = (s - 1) >> 1;
            j = li + 1;
            const int lab = ys[b * Ln + li];
            if (s >= 3) sk = (lab != 0) && (lab != ys[b * Ln + li - 1]);
        }
        jj[sl] = j;
        skipf[sl] = sk;
        a[sl] = (s == 0) ? eb[0] : (s == 1) ? eb[1] : NEGF;
    }

    const int inlen = hlen[b];
    float en[5];
    if (1 < inlen)
#pragma unroll
        for (int sl = 0; sl < 5; sl++) en[sl] = eb[Jn + jj[sl]];

    for (int t = 1; t < inlen; t++) {
        float e[5];
#pragma unroll
        for (int sl = 0; sl < 5; sl++) e[sl] = en[sl];
        if (t + 1 < inlen) {
            const float* et = eb + (size_t)(t + 1) * Jn;
#pragma unroll
            for (int sl = 0; sl < 5; sl++) en[sl] = et[jj[sl]];
        }
        float an[5];
#pragma unroll
        for (int sl = 0; sl < 5; sl++) {
            float up1 = __shfl_up_sync(0xffffffffu, a[sl], 1);
            float up2 = __shfl_up_sync(0xffffffffu, a[sl], 2);
            float pm1 = NEGF, pm2 = NEGF;
            if (sl > 0) {
                pm1 = __shfl_sync(0xffffffffu, a[sl - 1], 31);
                pm2 = __shfl_sync(0xffffffffu, a[sl - 1], 30);
            }
            float am1 = (lane == 0) ? pm1 : up1;
            float am2 = (lane == 0) ? pm2 : ((lane == 1) ? pm1 : up2);
            float comb = lae(a[sl], am1);
            if (skipf[sl]) comb = lae(comb, am2);
            an[sl] = comb + e[sl];
        }
#pragma unroll
        for (int sl = 0; sl < 5; sl++) a[sl] = an[sl];
    }

    __shared__ float sal[Smax + 3];
#pragma unroll
    for (int sl = 0; sl < 5; sl++) {
        const int s = sl * 32 + lane;
        if (s < Smax) sal[s] = a[sl];
    }
    __syncwarp();
    if (lane == 0) {
        const int s2 = 2 * ylen[b];
        g_ll[b] = -lae(sal[s2], sal[s2 - 1]);
    }
}

__global__ __launch_bounds__(32) void finalize_kernel(float* __restrict__ out) {
    const int lane = threadIdx.x;
    float v = (lane < Bn) ? g_ll[lane] : 0.f;
#pragma unroll
    for (int o = 16; o > 0; o >>= 1) v += __shfl_xor_sync(0xffffffffu, v, o);
    if (lane == 0) out[0] = v / (float)Bn;
}

// ----------------------------------------------------------------
extern "C" void kernel_launch(void* const* d_in, const int* in_sizes, int n_in,
                              void* d_out, int out_size) {
    const float* hs   = (const float*)d_in[0];
    const int*   hlen = (const int*)d_in[1];
    const int*   ys   = (const int*)d_in[2];
    const int*   ylen = (const int*)d_in[3];
    const float* Wm   = (const float*)d_in[4];
    const float* bias = (const float*)d_in[5];
    float* out = (float*)d_out;

    convA_kernel<<<(Mn * Hn) / (256 * 4), 256>>>(hs);
    convB_kernel<<<dim3(Vn / 32, Hn / 32), dim3(32, 8)>>>(Wm);
    rep_kernel<<<Bn, 96>>>(ys);
    gemm_mma_kernel<<<dim3(Vn / 128, Mn / 128), 256>>>(ys, bias);
    lse_emit_kernel<<<Mn / 8, 256>>>();
    ctc_dp_kernel<<<Bn, 32>>>(ys, hlen, ylen);
    finalize_kernel<<<1, 32>>>(out);
}